// round 6
// baseline (speedup 1.0000x reference)
#include <cuda_runtime.h>
#include <cuda_bf16.h>
#include <cstdint>

// Problem constants (from reference)
#define Bq 128
#define Nq 36
#define Dq 512
#define D4q 128          // Dq/4
#define Gq 2
#define NDq (Nq * Dq)
#define NEGV -1e10f

// Dynamic smem layout (bytes)
#define OFF_OBJ    0                         // float[36*512]  = 73728
#define OFF_SW     73728                     // float[2*512]   = 4096
#define OFF_T      77824                     // float[2*512]   = 4096
#define OFF_SWP    81920                     // float4[4][256] = 16384
#define OFF_TP     98304                     // float4[4][256] = 16384
#define OFF_LOGIT  114688                    // float[72]      = 288
#define OFF_WEIGHT 114976                    // float[72]      = 288
#define OFF_MBAR   115264                    // 8 B
#define OFF_FLAG   115272                    // 4 B
#define SMEM_TOTAL 115328

__device__ __forceinline__ uint32_t smem_u32(const void* p) {
    uint32_t a;
    asm("{ .reg .u64 t; cvta.to.shared.u64 t, %1; cvt.u32.u64 %0, t; }" : "=r"(a) : "l"(p));
    return a;
}

__device__ __forceinline__ void mbar_wait_acq(uint32_t mbar, uint32_t parity) {
    asm volatile(
        "{\n\t"
        ".reg .pred P;\n\t"
        "WAIT_%=:\n\t"
        "mbarrier.try_wait.parity.acquire.cta.shared::cta.b64 P, [%0], %1, 0x989680;\n\t"
        "@P bra.uni DONE_%=;\n\t"
        "bra.uni WAIT_%=;\n\t"
        "DONE_%=:\n\t"
        "}" :: "r"(mbar), "r"(parity) : "memory");
}

// One block per batch element, 1024 threads, occ 1.
// obj row (72KB) streams into smem via one cp.async.bulk while the CTA does
// W-only work (SW = sum_m W). Then T, logits, softmax, output all read smem.
// logits factorization:
//   logits[b,n,g] = sum_d o[n,d]^2 * SW[g,d] - sum_d o[n,d] * T[b,g,d]
__global__ __launch_bounds__(1024, 1)
void qgen_attn_kernel(const float* __restrict__ obj,   // [B, N, D]
                      const float* __restrict__ W,     // [G, N*D]
                      const float* __restrict__ bias,  // [G]
                      const unsigned char* __restrict__ mask_bytes, // [B,N]
                      float* __restrict__ out)         // [B, G*D]
{
    extern __shared__ __align__(16) char dsm[];
    float*  obj_s    = (float*)(dsm + OFF_OBJ);
    float*  SW_s     = (float*)(dsm + OFF_SW);
    float*  T_s      = (float*)(dsm + OFF_T);
    float4* swp      = (float4*)(dsm + OFF_SWP);   // [4][256]
    float4* tp       = (float4*)(dsm + OFF_TP);    // [4][256]
    float*  logit_s  = (float*)(dsm + OFF_LOGIT);
    float*  weight_s = (float*)(dsm + OFF_WEIGHT);
    int*    flag     = (int*)(dsm + OFF_FLAG);
    const uint32_t mbar = smem_u32(dsm + OFF_MBAR);

    const int b   = blockIdx.x;
    const int tid = threadIdx.x;      // 0..1023

    // ---- init mbarrier + flag ----
    if (tid == 0) {
        *flag = 0;
        asm volatile("mbarrier.init.shared.b64 [%0], %1;" :: "r"(mbar), "r"(1) : "memory");
    }
    __syncthreads();

    // ---- kick the bulk obj copy (one thread) ----
    const float* objb = obj + (size_t)b * NDq;
    if (tid == 0) {
        asm volatile("mbarrier.arrive.expect_tx.shared.b64 _, [%0], %1;"
                     :: "r"(mbar), "r"((uint32_t)(NDq * 4)) : "memory");
        asm volatile("cp.async.bulk.shared::cta.global.mbarrier::complete_tx::bytes "
                     "[%0], [%1], %2, [%3];"
                     :: "r"(smem_u32(obj_s)), "l"(objb),
                        "r"((uint32_t)(NDq * 4)), "r"(mbar) : "memory");
    }

    // ---- overlapped with the stream: mask dtype detection + SW (W only) ----
    if (tid < 256 && (tid & 3) != 0) {
        if (mask_bytes[tid] != 0) atomicOr(flag, 1);
    }

    const int col = tid & 255;        // (g,d4) column
    const int g1  = col >> 7;
    const int d4  = col & 127;
    const int ms  = tid >> 8;         // 0..3 slice of m (9 each)
    const float4* __restrict__ W4 = (const float4*)(W + (size_t)g1 * NDq);

    float4 wreg[9];
    float4 sw = make_float4(0.f, 0.f, 0.f, 0.f);
    #pragma unroll
    for (int j = 0; j < 9; j++) {
        wreg[j] = __ldg(W4 + (ms * 9 + j) * D4q + d4);
    }
    #pragma unroll
    for (int j = 0; j < 9; j++) {
        sw.x += wreg[j].x; sw.y += wreg[j].y; sw.z += wreg[j].z; sw.w += wreg[j].w;
    }
    swp[ms * 256 + col] = sw;

    // ---- wait for obj tile ----
    mbar_wait_acq(mbar, 0);

    // ---- T partials: reuse W (L1-hot) x obj (smem) ----
    {
        const float4* obj4s = (const float4*)obj_s;
        float4 t = make_float4(0.f, 0.f, 0.f, 0.f);
        #pragma unroll
        for (int j = 0; j < 9; j++) {
            const int m = ms * 9 + j;
            float4 w = __ldg(W4 + m * D4q + d4);   // L1 hit (same addrs as above)
            float4 o = obj4s[m * D4q + d4];
            t.x = fmaf(w.x, o.x, t.x);
            t.y = fmaf(w.y, o.y, t.y);
            t.z = fmaf(w.z, o.z, t.z);
            t.w = fmaf(w.w, o.w, t.w);
        }
        tp[ms * 256 + col] = t;
    }
    __syncthreads();

    // ---- reduce partials -> SW_s / T_s ----
    if (tid < 256) {
        float4 s0 = swp[tid], s1 = swp[256 + tid], s2 = swp[512 + tid], s3 = swp[768 + tid];
        float4 t0 = tp[tid],  t1 = tp[256 + tid],  t2 = tp[512 + tid],  t3 = tp[768 + tid];
        ((float4*)SW_s)[tid] = make_float4(s0.x+s1.x+s2.x+s3.x, s0.y+s1.y+s2.y+s3.y,
                                           s0.z+s1.z+s2.z+s3.z, s0.w+s1.w+s2.w+s3.w);
        ((float4*)T_s)[tid]  = make_float4(t0.x+t1.x+t2.x+t3.x, t0.y+t1.y+t2.y+t3.y,
                                           t0.z+t1.z+t2.z+t3.z, t0.w+t1.w+t2.w+t3.w);
    }
    __syncthreads();

    const bool mask_is_i32 = (*flag == 0);
    const int warp = tid >> 5;
    const int lane = tid & 31;

    // ---- Phase 2 (all smem): logits[n,g]; 72 warp-tasks / 32 warps ----
    for (int p = warp; p < Nq * Gq; p += 32) {
        const int n  = p >> 1;
        const int gg = p & 1;
        const float4* on4 = (const float4*)(obj_s + n * Dq);
        const float4* sw4 = (const float4*)(SW_s + gg * Dq);
        const float4* tg4 = (const float4*)(T_s  + gg * Dq);
        float acc = 0.f;
        #pragma unroll
        for (int k = 0; k < 4; k++) {
            const int i = k * 32 + lane;
            float4 o  = on4[i];
            float4 s  = sw4[i];
            float4 tt = tg4[i];
            acc = fmaf(o.x, fmaf(o.x, s.x, -tt.x), acc);
            acc = fmaf(o.y, fmaf(o.y, s.y, -tt.y), acc);
            acc = fmaf(o.z, fmaf(o.z, s.z, -tt.z), acc);
            acc = fmaf(o.w, fmaf(o.w, s.w, -tt.w), acc);
        }
        #pragma unroll
        for (int off = 16; off > 0; off >>= 1)
            acc += __shfl_down_sync(0xffffffffu, acc, off);
        if (lane == 0) logit_s[p] = acc + __ldg(bias + gg);
    }
    __syncthreads();

    // ---- Phase 3: masked softmax over n; warp 0 -> g=0, warp 16 -> g=1 ----
    if ((warp & 15) == 0) {
        const int gg = warp >> 4;
        const int n0 = lane, n1 = lane + 32;
        bool v0 = false, v1 = false;
        if (mask_is_i32) {
            const int* mi = (const int*)mask_bytes;
            v0 = mi[b * Nq + n0] != 0;
            if (n1 < Nq) v1 = mi[b * Nq + n1] != 0;
        } else {
            v0 = mask_bytes[b * Nq + n0] != 0;
            if (n1 < Nq) v1 = mask_bytes[b * Nq + n1] != 0;
        }
        float x0 = v0 ? logit_s[n0 * Gq + gg] : NEGV;
        float x1 = -1e30f;
        if (n1 < Nq) x1 = v1 ? logit_s[n1 * Gq + gg] : NEGV;
        float mx = fmaxf(x0, x1);
        #pragma unroll
        for (int off = 16; off > 0; off >>= 1)
            mx = fmaxf(mx, __shfl_xor_sync(0xffffffffu, mx, off));
        float e0 = __expf(x0 - mx);
        float e1 = (n1 < Nq) ? __expf(x1 - mx) : 0.f;
        float s = e0 + e1;
        #pragma unroll
        for (int off = 16; off > 0; off >>= 1)
            s += __shfl_xor_sync(0xffffffffu, s, off);
        const float inv = 1.f / s;
        weight_s[n0 * Gq + gg] = e0 * inv;
        if (n1 < Nq) weight_s[n1 * Gq + gg] = e1 * inv;
    }
    __syncthreads();

    // ---- Phase 4 (smem): out[b, g*D+d] = sum_n weight[n,g]*obj[n,d] ----
    {
        const int g = tid >> 9;
        const int d = tid & 511;
        float acc = 0.f;
        #pragma unroll
        for (int n = 0; n < Nq; n++)
            acc = fmaf(weight_s[n * Gq + g], obj_s[n * Dq + d], acc);
        out[(size_t)b * (Gq * Dq) + g * Dq + d] = acc;
    }
}

extern "C" void kernel_launch(void* const* d_in, const int* in_sizes, int n_in,
                              void* d_out, int out_size) {
    const float*         obj  = (const float*)d_in[0];         // [128, 36, 512]
    const float*         W    = (const float*)d_in[1];         // [2, 36*512]
    const float*         bias = (const float*)d_in[2];         // [2]
    const unsigned char* mask = (const unsigned char*)d_in[3]; // [128, 36]
    float* out = (float*)d_out;                                // [128, 1024]

    cudaFuncSetAttribute(qgen_attn_kernel,
                         cudaFuncAttributeMaxDynamicSharedMemorySize, SMEM_TOTAL);
    qgen_attn_kernel<<<Bq, 1024, SMEM_TOTAL>>>(obj, W, bias, mask, out);
}

// round 7
// speedup vs baseline: 1.0150x; 1.0150x over previous
#include <cuda_runtime.h>
#include <cuda_bf16.h>
#include <cstdint>

// Problem constants (from reference)
#define Bq 128
#define Nq 36
#define Dq 512
#define D4q 128          // Dq/4 (float4 per row)
#define Gq 2
#define NDq (Nq * Dq)
#define NCHUNK 4         // d-chunks of 128 floats (32 float4)
#define C4 32            // float4 per chunk
#define NEGV -1e10f

// Cross-kernel scratch: logit partials [B][NCHUNK][Nq*Gq]
__device__ float g_logit_part[Bq * NCHUNK * Nq * Gq];

// ---------------- K1: per-(b,chunk) T/SW + logit partials ----------------
// grid = B*NCHUNK, block = 256 (8 warps).
// logits factorization:
//   logit[b,n,g] = sum_d o[n,d]^2*SW[g,d] - o[n,d]*T[b,g,d],
//   SW[g,d] = sum_m W[g,m,d], T[b,g,d] = sum_m W[g,m,d]*o[b,m,d]
// This kernel produces the partial sum over d in its own 128-wide chunk.
__global__ __launch_bounds__(256, 6)
void qgen_k1(const float* __restrict__ obj,   // [B, N, D]
             const float* __restrict__ W)     // [G, N*D]
{
    __shared__ __align__(16) float4 objc[Nq][C4];       // 18 KB obj chunk
    __shared__ __align__(16) float4 tp [8][Gq][C4];     // 8 KB
    __shared__ __align__(16) float4 swp[8][Gq][C4];     // 8 KB
    __shared__ __align__(16) float4 Tf [Gq][C4];        // 1 KB
    __shared__ __align__(16) float4 SWf[Gq][C4];        // 1 KB

    const int b   = blockIdx.x >> 2;
    const int c   = blockIdx.x & 3;
    const int tid = threadIdx.x;          // 0..255
    const int d4l = tid & 31;             // float4 idx in chunk
    const int sl  = tid >> 5;             // 0..7 m-slice
    const int d4g = c * C4 + d4l;         // global float4 col

    const float4* __restrict__ obj4 = (const float4*)(obj + (size_t)b * NDq);
    const float4* __restrict__ W0   = (const float4*)W;
    const float4* __restrict__ W1   = (const float4*)(W + NDq);

    float4 t0 = make_float4(0,0,0,0), t1 = make_float4(0,0,0,0);
    float4 s0 = make_float4(0,0,0,0), s1 = make_float4(0,0,0,0);
    for (int m = sl; m < Nq; m += 8) {
        float4 o  = __ldg(obj4 + m * D4q + d4g);
        float4 w0 = __ldg(W0   + m * D4q + d4g);
        float4 w1 = __ldg(W1   + m * D4q + d4g);
        objc[m][d4l] = o;
        s0.x += w0.x; s0.y += w0.y; s0.z += w0.z; s0.w += w0.w;
        s1.x += w1.x; s1.y += w1.y; s1.z += w1.z; s1.w += w1.w;
        t0.x = fmaf(w0.x, o.x, t0.x); t0.y = fmaf(w0.y, o.y, t0.y);
        t0.z = fmaf(w0.z, o.z, t0.z); t0.w = fmaf(w0.w, o.w, t0.w);
        t1.x = fmaf(w1.x, o.x, t1.x); t1.y = fmaf(w1.y, o.y, t1.y);
        t1.z = fmaf(w1.z, o.z, t1.z); t1.w = fmaf(w1.w, o.w, t1.w);
    }
    tp [sl][0][d4l] = t0;  tp [sl][1][d4l] = t1;
    swp[sl][0][d4l] = s0;  swp[sl][1][d4l] = s1;
    __syncthreads();

    // reduce 8 slices (threads 0..63: g = tid>>5, d = tid&31)
    if (tid < 64) {
        const int g = tid >> 5, d = tid & 31;
        float4 ta = make_float4(0,0,0,0), sa = make_float4(0,0,0,0);
        #pragma unroll
        for (int s = 0; s < 8; s++) {
            float4 tv = tp[s][g][d], sv = swp[s][g][d];
            ta.x += tv.x; ta.y += tv.y; ta.z += tv.z; ta.w += tv.w;
            sa.x += sv.x; sa.y += sv.y; sa.z += sv.z; sa.w += sv.w;
        }
        Tf [g][d] = ta;
        SWf[g][d] = sa;
    }
    __syncthreads();

    // logit chunk-partials: 72 (n,g) tasks over 8 warps
    const int warp = tid >> 5, lane = tid & 31;
    float* __restrict__ dst = g_logit_part + ((size_t)b * NCHUNK + c) * (Nq * Gq);
    for (int p = warp; p < Nq * Gq; p += 8) {
        const int n = p >> 1, g = p & 1;
        float4 o  = objc[n][lane];
        float4 sw = SWf[g][lane];
        float4 tt = Tf[g][lane];
        float acc;
        acc  = o.x * fmaf(o.x, sw.x, -tt.x);
        acc  = fmaf(o.y, fmaf(o.y, sw.y, -tt.y), acc);
        acc  = fmaf(o.z, fmaf(o.z, sw.z, -tt.z), acc);
        acc  = fmaf(o.w, fmaf(o.w, sw.w, -tt.w), acc);
        #pragma unroll
        for (int off = 16; off > 0; off >>= 1)
            acc += __shfl_down_sync(0xffffffffu, acc, off);
        if (lane == 0) dst[p] = acc;
    }
}

// ---------------- K2: logits sum + softmax + output chunk ----------------
// grid = B*NCHUNK, block = 256.
__global__ __launch_bounds__(256, 6)
void qgen_k2(const float* __restrict__ obj,   // [B, N, D]
             const float* __restrict__ bias,  // [G]
             const unsigned char* __restrict__ mask_bytes, // [B,N]
             float* __restrict__ out)         // [B, G*D]
{
    __shared__ float logit_s[Nq * Gq];
    __shared__ float weight_s[Nq * Gq];
    __shared__ __align__(16) float4 op[4][Gq][C4];  // 4 KB output partials
    __shared__ int flag;

    const int b   = blockIdx.x >> 2;
    const int c   = blockIdx.x & 3;
    const int tid = threadIdx.x;

    if (tid == 0) flag = 0;
    __syncthreads();

    // mask dtype detection (int32 => bytes at offset%4!=0 all zero)
    if (tid < 256 && (tid & 3) != 0) {
        if (mask_bytes[tid] != 0) atomicOr(&flag, 1);
    }

    // sum the 4 chunk partials in fixed order (deterministic) + bias
    if (tid < Nq * Gq) {
        const float* src = g_logit_part + (size_t)b * NCHUNK * (Nq * Gq) + tid;
        float v = src[0];
        v += src[1 * Nq * Gq];
        v += src[2 * Nq * Gq];
        v += src[3 * Nq * Gq];
        logit_s[tid] = v + __ldg(bias + (tid & 1));
    }
    __syncthreads();

    const int warp = tid >> 5, lane = tid & 31;
    const bool mask_is_i32 = (flag == 0);

    // masked softmax over n: warp 0 -> g=0, warp 1 -> g=1
    if (warp < Gq) {
        const int g = warp;
        const int n0 = lane, n1 = lane + 32;
        bool v0 = false, v1 = false;
        if (mask_is_i32) {
            const int* mi = (const int*)mask_bytes;
            v0 = mi[b * Nq + n0] != 0;
            if (n1 < Nq) v1 = mi[b * Nq + n1] != 0;
        } else {
            v0 = mask_bytes[b * Nq + n0] != 0;
            if (n1 < Nq) v1 = mask_bytes[b * Nq + n1] != 0;
        }
        float x0 = v0 ? logit_s[n0 * Gq + g] : NEGV;
        float x1 = -1e30f;
        if (n1 < Nq) x1 = v1 ? logit_s[n1 * Gq + g] : NEGV;
        float mx = fmaxf(x0, x1);
        #pragma unroll
        for (int off = 16; off > 0; off >>= 1)
            mx = fmaxf(mx, __shfl_xor_sync(0xffffffffu, mx, off));
        float e0 = __expf(x0 - mx);
        float e1 = (n1 < Nq) ? __expf(x1 - mx) : 0.f;
        float s = e0 + e1;
        #pragma unroll
        for (int off = 16; off > 0; off >>= 1)
            s += __shfl_xor_sync(0xffffffffu, s, off);
        const float inv = 1.f / s;
        weight_s[n0 * Gq + g] = e0 * inv;
        if (n1 < Nq) weight_s[n1 * Gq + g] = e1 * inv;
    }
    __syncthreads();

    // output chunk: t = g*128 + nsl*32 + d4l ; partial over n = nsl..36 step 4
    {
        const int g   = tid >> 7;         // 0..1
        const int nsl = (tid >> 5) & 3;   // 0..3
        const int d4l = tid & 31;
        const int d4g = c * C4 + d4l;
        const float4* __restrict__ obj4 = (const float4*)(obj + (size_t)b * NDq);
        float4 acc = make_float4(0,0,0,0);
        for (int n = nsl; n < Nq; n += 4) {
            float wn = weight_s[n * Gq + g];
            float4 o = __ldg(obj4 + n * D4q + d4g);
            acc.x = fmaf(wn, o.x, acc.x);
            acc.y = fmaf(wn, o.y, acc.y);
            acc.z = fmaf(wn, o.z, acc.z);
            acc.w = fmaf(wn, o.w, acc.w);
        }
        op[nsl][g][d4l] = acc;
    }
    __syncthreads();

    if (tid < 64) {
        const int g = tid >> 5, d4l = tid & 31;
        float4 a0 = op[0][g][d4l], a1 = op[1][g][d4l], a2 = op[2][g][d4l], a3 = op[3][g][d4l];
        float4 r = make_float4(a0.x+a1.x+a2.x+a3.x, a0.y+a1.y+a2.y+a3.y,
                               a0.z+a1.z+a2.z+a3.z, a0.w+a1.w+a2.w+a3.w);
        float4* o4 = (float4*)(out + (size_t)b * (Gq * Dq) + g * Dq + c * 128);
        o4[d4l] = r;
    }
}

extern "C" void kernel_launch(void* const* d_in, const int* in_sizes, int n_in,
                              void* d_out, int out_size) {
    const float*         obj  = (const float*)d_in[0];         // [128, 36, 512]
    const float*         W    = (const float*)d_in[1];         // [2, 36*512]
    const float*         bias = (const float*)d_in[2];         // [2]
    const unsigned char* mask = (const unsigned char*)d_in[3]; // [128, 36]
    float* out = (float*)d_out;                                // [128, 1024]

    qgen_k1<<<Bq * NCHUNK, 256>>>(obj, W);
    qgen_k2<<<Bq * NCHUNK, 256>>>(obj, bias, mask, out);
}

// round 8
// speedup vs baseline: 1.1871x; 1.1696x over previous
#include <cuda_runtime.h>
#include <cuda_bf16.h>
#include <cstdint>

// Problem constants (from reference)
#define Bq 128
#define Nq 36
#define Dq 512
#define D4q 128          // Dq/4
#define Gq 2
#define NDq (Nq * Dq)
#define NEGV -1e10f

// Dynamic smem layout (bytes, 16B aligned)
#define OFF_OBJ    0                   // float4[36*128]   = 73728
#define OFF_SWP    73728               // float4[4][256]   = 16384
#define OFF_TP     90112               // float4[4][256]   = 16384
#define OFF_SWF    106496              // float4[256]      = 4096
#define OFF_TF     110592              // float4[256]      = 4096
#define OFF_LOGIT  114688              // float[72]        = 288
#define OFF_WEIGHT 114976              // float[72]        = 288
#define OFF_MROW   115264              // int[36]          = 144
#define OFF_BIAS   115408              // float[2]         = 8
#define OFF_FLAG   115416              // int              = 4
#define SMEM_TOTAL 115424

// One block per batch element, 1024 threads, single wave (128 CTAs).
// Critical-path-minimized: one global load burst, then pure smem/shuffle.
// logits factorization:
//   logit[b,n,g] = sum_d o[n,d]^2*SW[g,d] - o[n,d]*T[b,g,d]
//   SW[g,d] = sum_m W[g,m,d], T[b,g,d] = sum_m W[g,m,d]*o[b,m,d]
__global__ __launch_bounds__(1024, 1)
void qgen_attn_kernel(const float* __restrict__ obj,   // [B, N, D]
                      const float* __restrict__ W,     // [G, N*D]
                      const float* __restrict__ bias,  // [G]
                      const unsigned char* __restrict__ mask_bytes, // [B,N]
                      float* __restrict__ out)         // [B, G*D]
{
    extern __shared__ __align__(16) char dsm[];
    float4* obj_s4   = (float4*)(dsm + OFF_OBJ);
    float4* swp      = (float4*)(dsm + OFF_SWP);
    float4* tp       = (float4*)(dsm + OFF_TP);
    float4* SWf      = (float4*)(dsm + OFF_SWF);   // [g*128 + d4]
    float4* Tf       = (float4*)(dsm + OFF_TF);
    float*  logit_s  = (float*)(dsm + OFF_LOGIT);
    float*  weight_s = (float*)(dsm + OFF_WEIGHT);
    int*    mrow_s   = (int*)(dsm + OFF_MROW);
    float*  bias_s   = (float*)(dsm + OFF_BIAS);
    volatile int* flag = (int*)(dsm + OFF_FLAG);

    const int b   = blockIdx.x;
    const int tid = threadIdx.x;      // 0..1023

    if (tid == 0) *flag = 0;
    __syncthreads();                                  // BAR0 (flag init)

    // mask dtype detection: bytes at offset%4!=0 are all zero iff int32.
    // In-bounds for both interpretations. Plain store (race-same-value OK).
    if (tid < 256 && (tid & 3) != 0) {
        if (mask_bytes[tid] != 0) *flag = 1;
    }

    // bias prefetch (unconditional, tiny): hold in reg, commit before BAR3.
    float bias_v = 0.f;
    const bool is_biaspref = (tid >= 612 && tid < 614);
    if (is_biaspref) bias_v = __ldg(bias + (tid - 612));

    // ---- Phase 1: the only global burst. obj+W LDG, obj -> smem, SW/T partials ----
    const int col = tid & 255;         // (g1,d4)
    const int g1  = col >> 7;
    const int d4  = col & 127;
    const int ms  = tid >> 8;          // 0..3, 9 m's each
    const float4* __restrict__ W4    = (const float4*)(W + (size_t)g1 * NDq);
    const float4* __restrict__ obj4g = (const float4*)(obj + (size_t)b * NDq);

    {
        float4 sw = make_float4(0,0,0,0), t = make_float4(0,0,0,0);
        #pragma unroll
        for (int j = 0; j < 9; j++) {
            const int m = ms * 9 + j;
            float4 w = __ldg(W4    + m * D4q + d4);
            float4 o = __ldg(obj4g + m * D4q + d4);
            if (g1 == 0) obj_s4[m * D4q + d4] = o;
            sw.x += w.x; sw.y += w.y; sw.z += w.z; sw.w += w.w;
            t.x = fmaf(w.x, o.x, t.x);
            t.y = fmaf(w.y, o.y, t.y);
            t.z = fmaf(w.z, o.z, t.z);
            t.w = fmaf(w.w, o.w, t.w);
        }
        swp[ms * 256 + col] = sw;
        tp [ms * 256 + col] = t;
    }
    __syncthreads();                                  // BAR1 (obj_s, partials, flag ready)

    // mask-row prefetch by logits-idle threads (gid >= 72): issue now,
    // commit to smem just before BAR3 (latency hidden behind reduce+logits).
    int mrow_v = 0;
    const bool is_maskpref = (tid >= 576 && tid < 576 + Nq);
    if (is_maskpref) {
        const int i = tid - 576;
        if (*flag == 0) mrow_v = __ldg((const int*)mask_bytes + b * Nq + i);
        else            mrow_v = (int)__ldg(mask_bytes + b * Nq + i);
    }

    // ---- Phase 2: reduce 4 slices -> SW/T final ----
    if (tid < 256) {
        float4 s0 = swp[tid], s1 = swp[256+tid], s2 = swp[512+tid], s3 = swp[768+tid];
        float4 t0 = tp[tid],  t1 = tp[256+tid],  t2 = tp[512+tid],  t3 = tp[768+tid];
        SWf[tid] = make_float4(s0.x+s1.x+s2.x+s3.x, s0.y+s1.y+s2.y+s3.y,
                               s0.z+s1.z+s2.z+s3.z, s0.w+s1.w+s2.w+s3.w);
        Tf[tid]  = make_float4(t0.x+t1.x+t2.x+t3.x, t0.y+t1.y+t2.y+t3.y,
                               t0.z+t1.z+t2.z+t3.z, t0.w+t1.w+t2.w+t3.w);
    }
    __syncthreads();                                  // BAR2

    // ---- Phase 3: logits, single round. 128 8-lane groups, 72 active ----
    {
        const int gid = tid >> 3;     // 0..127
        const int l   = tid & 7;
        if (gid < Nq * Gq) {
            const int n  = gid >> 1;
            const int gg = gid & 1;
            const float4* on4 = obj_s4 + n * D4q;
            const float4* sw4 = SWf + gg * D4q;
            const float4* tg4 = Tf  + gg * D4q;
            float acc = 0.f;
            #pragma unroll
            for (int k = 0; k < 16; k++) {
                const int i = k * 8 + l;
                float4 o  = on4[i];
                float4 s  = sw4[i];
                float4 tt = tg4[i];
                acc = fmaf(o.x, fmaf(o.x, s.x, -tt.x), acc);
                acc = fmaf(o.y, fmaf(o.y, s.y, -tt.y), acc);
                acc = fmaf(o.z, fmaf(o.z, s.z, -tt.z), acc);
                acc = fmaf(o.w, fmaf(o.w, s.w, -tt.w), acc);
            }
            acc += __shfl_xor_sync(0xffffffffu, acc, 4, 8);
            acc += __shfl_xor_sync(0xffffffffu, acc, 2, 8);
            acc += __shfl_xor_sync(0xffffffffu, acc, 1, 8);
            if (l == 0) logit_s[gid] = acc;
        }
    }
    // commit prefetches (their LDG latency was covered by reduce+logits)
    if (is_maskpref) mrow_s[tid - 576] = mrow_v;
    if (is_biaspref) bias_s[tid - 612] = bias_v;
    __syncthreads();                                  // BAR3

    // ---- Phase 4: masked softmax over n; warp 0 -> g=0, warp 16 -> g=1 ----
    const int warp = tid >> 5, lane = tid & 31;
    if ((warp & 15) == 0) {
        const int g  = warp >> 4;
        const int n0 = lane, n1 = lane + 32;
        float x0 = mrow_s[n0] ? (logit_s[n0 * Gq + g] + bias_s[g]) : NEGV;
        float x1 = -1e30f;
        if (n1 < Nq) x1 = mrow_s[n1] ? (logit_s[n1 * Gq + g] + bias_s[g]) : NEGV;
        float mx = fmaxf(x0, x1);
        #pragma unroll
        for (int off = 16; off > 0; off >>= 1)
            mx = fmaxf(mx, __shfl_xor_sync(0xffffffffu, mx, off));
        float e0 = __expf(x0 - mx);
        float e1 = (n1 < Nq) ? __expf(x1 - mx) : 0.f;
        float s = e0 + e1;
        #pragma unroll
        for (int off = 16; off > 0; off >>= 1)
            s += __shfl_xor_sync(0xffffffffu, s, off);
        const float inv = 1.f / s;
        weight_s[n0 * Gq + g] = e0 * inv;
        if (n1 < Nq) weight_s[n1 * Gq + g] = e1 * inv;
    }
    __syncthreads();                                  // BAR4

    // ---- Phase 5: output. 256 threads, all smem, one STG.128 each ----
    if (tid < 256) {
        const int g   = tid >> 7;
        const int d4o = tid & 127;
        float4 acc = make_float4(0,0,0,0);
        #pragma unroll
        for (int n = 0; n < Nq; n++) {
            const float wn = weight_s[n * Gq + g];
            float4 o = obj_s4[n * D4q + d4o];
            acc.x = fmaf(wn, o.x, acc.x);
            acc.y = fmaf(wn, o.y, acc.y);
            acc.z = fmaf(wn, o.z, acc.z);
            acc.w = fmaf(wn, o.w, acc.w);
        }
        ((float4*)(out + (size_t)b * (Gq * Dq)))[g * D4q + d4o] = acc;
    }
}

extern "C" void kernel_launch(void* const* d_in, const int* in_sizes, int n_in,
                              void* d_out, int out_size) {
    const float*         obj  = (const float*)d_in[0];         // [128, 36, 512]
    const float*         W    = (const float*)d_in[1];         // [2, 36*512]
    const float*         bias = (const float*)d_in[2];         // [2]
    const unsigned char* mask = (const unsigned char*)d_in[3]; // [128, 36]
    float* out = (float*)d_out;                                // [128, 1024]

    cudaFuncSetAttribute(qgen_attn_kernel,
                         cudaFuncAttributeMaxDynamicSharedMemorySize, SMEM_TOTAL);
    qgen_attn_kernel<<<Bq, 1024, SMEM_TOTAL>>>(obj, W, bias, mask, out);
}